// round 4
// baseline (speedup 1.0000x reference)
#include <cuda_runtime.h>
#include <cuda_bf16.h>
#include <cstdint>

#define BB 16
#define CC 256
#define TT 4096
#define KCODES 1024
#define NTOK (BB*TT)
#define QN (BB*CC*TT)
#define MARGIN 2e-3f
#define MAXCAND 16

__device__ float  g_fnorm[NTOK];
__device__ float  g_enorm[KCODES];
__device__ int    g_idx[NTOK];
__device__ double g_loss;
__device__ float  g_xt[(size_t)NTOK * CC];
__device__ __nv_bfloat16 g_xhi[(size_t)NTOK * CC];
__device__ __nv_bfloat16 g_cbhi[KCODES * CC];
__device__ int g_cand[NTOK * MAXCAND];
__device__ int g_ncand[NTOK];

// ---------------- portable PTX helpers (sm_80+ ISA, no 'a' target needed) ----
__device__ __forceinline__ uint32_t smem_u32(const void* p) {
    uint32_t a;
    asm("{ .reg .u64 t; cvta.to.shared.u64 t, %1; cvt.u32.u64 %0, t; }" : "=r"(a) : "l"(p));
    return a;
}
#define SW128(o) ((o) ^ (((o) >> 3) & 0x70))
#define CP_ASYNC16(dst, src) \
    asm volatile("cp.async.cg.shared.global [%0], [%1], 16;" :: "r"(dst), "l"(src) : "memory")
#define CP_COMMIT()  asm volatile("cp.async.commit_group;" ::: "memory")
#define CP_WAIT1()   asm volatile("cp.async.wait_group 1;" ::: "memory")
#define CP_WAIT0()   asm volatile("cp.async.wait_group 0;" ::: "memory")

__device__ __forceinline__ void ldm_x4(uint32_t& r0, uint32_t& r1, uint32_t& r2,
                                       uint32_t& r3, uint32_t addr) {
    asm volatile("ldmatrix.sync.aligned.m8n8.x4.shared.b16 {%0,%1,%2,%3}, [%4];"
                 : "=r"(r0), "=r"(r1), "=r"(r2), "=r"(r3) : "r"(addr));
}
__device__ __forceinline__ void hmma(float* c, const uint32_t* a, uint32_t b0, uint32_t b1) {
    asm volatile("mma.sync.aligned.m16n8k16.row.col.f32.bf16.bf16.f32 "
                 "{%0,%1,%2,%3}, {%4,%5,%6,%7}, {%8,%9}, {%0,%1,%2,%3};"
                 : "+f"(c[0]), "+f"(c[1]), "+f"(c[2]), "+f"(c[3])
                 : "r"(a[0]), "r"(a[1]), "r"(a[2]), "r"(a[3]), "r"(b0), "r"(b1));
}
__device__ __forceinline__ unsigned packf(float d) {
    unsigned u = __float_as_uint(d);
    return (u & 0x80000000u) ? ~u : (u | 0x80000000u);
}
__device__ __forceinline__ float unpackf(unsigned p) {
    unsigned u = (p & 0x80000000u) ? (p ^ 0x80000000u) : ~p;
    return __uint_as_float(u);
}

// ---------------- smem layout (dynamic) ----------------
#define OFF_A     0          // 2 x 16384 (128 tok x 64 bf16, SW128)
#define OFF_B     32768      // 2 x 16384 (128 code x 64 bf16, SW128)
#define OFF_SEN   65536      // 128 f
#define OFF_SFN   66048      // 128 f
#define OFF_SMIN  66560      // 128 u32
#define OFF_SCNT  67072      // 128 i32
#define OFF_SCAND 67584      // 128*16 i32
#define SMEM_BYTES 75776

// ---------------- small kernels ----------------
__global__ void zero_loss_kernel() { g_loss = 0.0; }

__global__ void enorm_kernel(const float* __restrict__ cb) {
    int k = blockIdx.x * blockDim.x + threadIdx.x;
    if (k >= KCODES) return;
    const float4* row = reinterpret_cast<const float4*>(cb + (size_t)k * CC);
    float s = 0.f;
    #pragma unroll
    for (int i = 0; i < CC / 4; i++) {
        float4 v = row[i];
        s += v.x * v.x + v.y * v.y + v.z * v.z + v.w * v.w;
    }
    g_enorm[k] = s;
}

// bit-identical to round-1 fnorm (rel_err 0.0 depends on this chain)
__global__ void fnorm_kernel(const float* __restrict__ x) {
    int tok = blockIdx.x * blockDim.x + threadIdx.x;
    int b = tok >> 12;
    int t = tok & (TT - 1);
    const float* p = x + (size_t)b * CC * TT + t;
    float s = 0.f;
    #pragma unroll 8
    for (int c = 0; c < CC; c++) {
        float v = p[(size_t)c * TT];
        s += v * v;
    }
    g_fnorm[tok] = s;
}

__global__ void cbsplit_kernel(const float* __restrict__ cb) {
    int i = blockIdx.x * blockDim.x + threadIdx.x;
    if (i >= KCODES * CC) return;
    g_cbhi[i] = __float2bfloat16(cb[i]);
}

// transpose x (B,C,T) -> token-major fp32 (exact, for rescore) + bf16 hi
__global__ __launch_bounds__(256) void xsplit_kernel(const float* __restrict__ x) {
    __shared__ float s[32][33];
    int t0 = blockIdx.x * 32, c0 = blockIdx.y * 32, b = blockIdx.z;
    int tl = threadIdx.x & 31, wr = threadIdx.x >> 5;
    const float* xb = x + (size_t)b * CC * TT;
    #pragma unroll
    for (int k = 0; k < 4; k++) {
        int c = wr + k * 8;
        s[c][tl] = xb[(size_t)(c0 + c) * TT + t0 + tl];
    }
    __syncthreads();
    #pragma unroll
    for (int k = 0; k < 4; k++) {
        int tt = wr + k * 8;
        float v = s[tl][tt];
        size_t o = (size_t)(b * TT + t0 + tt) * CC + c0 + tl;
        g_xt[o] = v;
        g_xhi[o] = __float2bfloat16(v);
    }
}

// ---------------- HMMA GEMM + running-min candidate collection ----------------
__device__ __forceinline__ void issue_load(uint32_t sb, int token0, int idx,
                                           int slot, int tid) {
    int nt = idx >> 2, kc = idx & 3;
    const char* asrc = (const char*)g_xhi + (size_t)token0 * 512 + (size_t)kc * 128;
    const char* bsrc = (const char*)g_cbhi + (size_t)nt * 128 * 512 + (size_t)kc * 128;
    #pragma unroll
    for (int i = 0; i < 4; i++) {
        int e = i * 256 + tid;
        int r = e >> 3, u = e & 7;
        CP_ASYNC16(sb + OFF_A + slot * 16384 + SW128(r * 128 + u * 16),
                   asrc + (size_t)r * 512 + u * 16);
    }
    #pragma unroll
    for (int i = 0; i < 4; i++) {
        int e = i * 256 + tid;
        int r = e >> 3, u = e & 7;
        CP_ASYNC16(sb + OFF_B + slot * 16384 + SW128(r * 128 + u * 16),
                   bsrc + (size_t)r * 512 + u * 16);
    }
    CP_COMMIT();
}

__global__ void __launch_bounds__(256, 2) argmin_hmma_kernel() {
    extern __shared__ __align__(1024) char smb[];
    const uint32_t sb = smem_u32(smb);
    float*    sen   = (float*)(smb + OFF_SEN);
    float*    sfn   = (float*)(smb + OFF_SFN);
    unsigned* smin  = (unsigned*)(smb + OFF_SMIN);
    int*      scnt  = (int*)(smb + OFF_SCNT);
    int*      scand = (int*)(smb + OFF_SCAND);

    const int tid = threadIdx.x, lane = tid & 31, wid = tid >> 5;
    const int wm = wid & 3, wn = wid >> 2;     // warp grid 4 x 2, warp tile 32x64
    const int token0 = blockIdx.x * 128;

    if (tid < 128) {
        smin[tid] = 0xFFFFFFFFu;
        scnt[tid] = 0;
        sfn[tid] = g_fnorm[token0 + tid];
    }
    issue_load(sb, token0, 0, 0, tid);
    __syncthreads();

    int   rowm[2][2];
    float fnv[2][2];
    #pragma unroll
    for (int mi = 0; mi < 2; mi++)
        #pragma unroll
        for (int h = 0; h < 2; h++) {
            rowm[mi][h] = wm * 32 + mi * 16 + (lane >> 2) + h * 8;
            fnv[mi][h] = sfn[rowm[mi][h]];
        }

    float c[2][8][4];

    for (int idx = 0; idx < 32; idx++) {
        const int slot = idx & 1;
        const int nt = idx >> 2, kc = idx & 3;
        if (idx + 1 < 32) { issue_load(sb, token0, idx + 1, (idx + 1) & 1, tid); CP_WAIT1(); }
        else              { CP_WAIT0(); }
        __syncthreads();

        if (kc == 0) {
            #pragma unroll
            for (int mi = 0; mi < 2; mi++)
                #pragma unroll
                for (int ni = 0; ni < 8; ni++)
                    #pragma unroll
                    for (int e = 0; e < 4; e++) c[mi][ni][e] = 0.f;
        }

        const uint32_t Ab = sb + OFF_A + slot * 16384;
        const uint32_t Bb = sb + OFF_B + slot * 16384;
        #pragma unroll
        for (int s = 0; s < 4; s++) {
            uint32_t a[2][4];
            #pragma unroll
            for (int mi = 0; mi < 2; mi++) {
                uint32_t addr = Ab + SW128((wm * 32 + mi * 16 + (lane & 15)) * 128
                                           + (lane >> 4) * 16 + s * 32);
                ldm_x4(a[mi][0], a[mi][1], a[mi][2], a[mi][3], addr);
            }
            #pragma unroll
            for (int p = 0; p < 4; p++) {
                uint32_t b0, b1, b2, b3;
                int r = wn * 64 + p * 16 + (lane & 7) + ((lane >> 4) & 1) * 8;
                uint32_t addr = Bb + SW128(r * 128 + ((lane >> 3) & 1) * 16 + s * 32);
                ldm_x4(b0, b1, b2, b3, addr);
                hmma(c[0][2 * p],     a[0], b0, b1);
                hmma(c[0][2 * p + 1], a[0], b2, b3);
                hmma(c[1][2 * p],     a[1], b0, b1);
                hmma(c[1][2 * p + 1], a[1], b2, b3);
            }
        }

        if (kc == 3) {
            // ---- epilogue for N-tile nt (codes nt*128 .. +127) ----
            if (tid < 128) sen[tid] = g_enorm[nt * 128 + tid];
            __syncthreads();
            unsigned lmin[2][2] = {{0xFFFFFFFFu, 0xFFFFFFFFu}, {0xFFFFFFFFu, 0xFFFFFFFFu}};
            #pragma unroll
            for (int mi = 0; mi < 2; mi++)
                #pragma unroll
                for (int ni = 0; ni < 8; ni++)
                    #pragma unroll
                    for (int e = 0; e < 4; e++) {
                        int col = wn * 64 + ni * 8 + (lane & 3) * 2 + (e & 1);
                        float d = (fnv[mi][e >> 1] - 2.0f * c[mi][ni][e]) + sen[col];
                        unsigned pk = packf(d);
                        if (pk < lmin[mi][e >> 1]) lmin[mi][e >> 1] = pk;
                    }
            #pragma unroll
            for (int mi = 0; mi < 2; mi++)
                #pragma unroll
                for (int h = 0; h < 2; h++)
                    atomicMin(&smin[rowm[mi][h]], lmin[mi][h]);
            __syncthreads();
            float thr[2][2];
            #pragma unroll
            for (int mi = 0; mi < 2; mi++)
                #pragma unroll
                for (int h = 0; h < 2; h++)
                    thr[mi][h] = unpackf(smin[rowm[mi][h]]) + MARGIN;
            #pragma unroll
            for (int mi = 0; mi < 2; mi++)
                #pragma unroll
                for (int ni = 0; ni < 8; ni++)
                    #pragma unroll
                    for (int e = 0; e < 4; e++) {
                        int col = wn * 64 + ni * 8 + (lane & 3) * 2 + (e & 1);
                        float d = (fnv[mi][e >> 1] - 2.0f * c[mi][ni][e]) + sen[col];
                        if (d <= thr[mi][e >> 1]) {
                            int row = rowm[mi][e >> 1];
                            int pos = atomicAdd(&scnt[row], 1);
                            if (pos < MAXCAND)
                                scand[row * MAXCAND + pos] = nt * 128 + col;
                        }
                    }
        }
        __syncthreads();
    }

    if (tid < 128) {
        int cnt = scnt[tid];
        g_ncand[token0 + tid] = cnt;
        int n = cnt < MAXCAND ? cnt : MAXCAND;
        for (int i = 0; i < n; i++)
            g_cand[(token0 + tid) * MAXCAND + i] = scand[tid * MAXCAND + i];
    }
}

// ---------------- exact rescore (bit-identical to round-1 arithmetic) ----------
__global__ __launch_bounds__(128) void rescore_kernel(
    const float* __restrict__ cb, float* __restrict__ out_idx)
{
    __shared__ float xs[32][256];
    int tok0 = blockIdx.x * 32;
    for (int e = threadIdx.x; e < 32 * 256; e += 128)
        xs[e >> 8][e & 255] = g_xt[(size_t)tok0 * CC + e];
    __syncthreads();
    if (threadIdx.x >= 32) return;
    int tok = tok0 + threadIdx.x;
    float fnv = g_fnorm[tok];
    int cnt = g_ncand[tok];
    unsigned long long best = ~0ull;
    const float* xr = xs[threadIdx.x];
    if (cnt > MAXCAND) {
        for (int j = 0; j < KCODES; j++) {
            float acc = 0.f;
            const float* cr = cb + (size_t)j * CC;
            #pragma unroll 8
            for (int cc = 0; cc < CC; cc++) acc = fmaf(xr[cc], cr[cc], acc);
            float d = (fnv - 2.0f * acc) + g_enorm[j];
            unsigned u = __float_as_uint(d);
            u = (u & 0x80000000u) ? ~u : (u | 0x80000000u);
            unsigned long long key = ((unsigned long long)u << 32) | (unsigned)j;
            if (key < best) best = key;
        }
    } else {
        for (int i = 0; i < cnt; i++) {
            int j = g_cand[tok * MAXCAND + i];
            float acc = 0.f;
            const float* cr = cb + (size_t)j * CC;
            #pragma unroll 8
            for (int cc = 0; cc < CC; cc++) acc = fmaf(xr[cc], cr[cc], acc);
            float d = (fnv - 2.0f * acc) + g_enorm[j];
            unsigned u = __float_as_uint(d);
            u = (u & 0x80000000u) ? ~u : (u | 0x80000000u);
            unsigned long long key = ((unsigned long long)u << 32) | (unsigned)j;
            if (key < best) best = key;
        }
    }
    int idx = (int)(best & 0xffffffffu);
    g_idx[tok] = idx;
    if (out_idx) out_idx[tok] = (float)idx;
}

// ---------------- gather + loss ----------------
__global__ __launch_bounds__(256) void gather_kernel(
    const float* __restrict__ x, const float* __restrict__ cb,
    float* __restrict__ out_q)
{
    __shared__ float qs[32][257];
    __shared__ int   sidx[32];
    __shared__ float red[8];
    const int tid = threadIdx.x;
    const int t0 = blockIdx.x * 32;
    const int b = blockIdx.y;
    if (tid < 32) sidx[tid] = g_idx[b * TT + t0 + tid];
    __syncthreads();
    #pragma unroll
    for (int r = 0; r < 32; r++)
        qs[r][tid] = cb[(size_t)sidx[r] * CC + tid];
    __syncthreads();
    float lsum = 0.f;
    const float* xb = x + (size_t)b * CC * TT + t0;
    float* ob = out_q + (size_t)b * CC * TT + t0;
    #pragma unroll
    for (int r = 0; r < 32; r++) {
        int c = (tid >> 5) + 8 * r;
        int tj = tid & 31;
        float q = qs[tj][c];
        float xv = xb[(size_t)c * TT + tj];
        float diff = q - xv;
        lsum += diff * diff;
        ob[(size_t)c * TT + tj] = xv + diff;
    }
    #pragma unroll
    for (int o = 16; o; o >>= 1) lsum += __shfl_down_sync(0xffffffffu, lsum, o);
    if ((tid & 31) == 0) red[tid >> 5] = lsum;
    __syncthreads();
    if (tid == 0) {
        float s = 0.f;
        #pragma unroll
        for (int i = 0; i < 8; i++) s += red[i];
        atomicAdd(&g_loss, (double)s);
    }
}

__global__ void finalize_kernel(float* out_loss) {
    *out_loss = (float)(1.25 * g_loss / (double)QN);
}

extern "C" void kernel_launch(void* const* d_in, const int* in_sizes, int n_in,
                              void* d_out, int out_size) {
    const float* x  = (const float*)d_in[0];
    const float* cb = (const float*)d_in[1];
    if (n_in >= 2 && in_sizes[0] == KCODES * CC && in_sizes[1] == QN) {
        const float* tmp = x; x = cb; cb = tmp;
    }
    float* out = (float*)d_out;
    float* out_q = out;
    float* out_idx = nullptr;
    float* out_loss = nullptr;
    if (out_size >= QN + NTOK)     out_idx  = out + QN;
    if (out_size >= QN + NTOK + 1) out_loss = out + QN + NTOK;

    cudaFuncSetAttribute(argmin_hmma_kernel,
                         cudaFuncAttributeMaxDynamicSharedMemorySize, SMEM_BYTES);

    zero_loss_kernel<<<1, 1>>>();
    enorm_kernel<<<KCODES / 256, 256>>>(cb);
    fnorm_kernel<<<NTOK / 256, 256>>>(x);
    cbsplit_kernel<<<(KCODES * CC) / 256, 256>>>(cb);
    xsplit_kernel<<<dim3(TT / 32, CC / 32, BB), 256>>>(x);
    argmin_hmma_kernel<<<NTOK / 128, 256, SMEM_BYTES>>>();
    rescore_kernel<<<NTOK / 32, 128>>>(cb, out_idx);
    gather_kernel<<<dim3(TT / 32, BB), 256>>>(x, cb, out_q);
    if (out_loss) finalize_kernel<<<1, 1>>>(out_loss);
}